// round 15
// baseline (speedup 1.0000x reference)
#include <cuda_runtime.h>
#include <math.h>

#define NPOS 512
#define NALL 1024
#define DIM  512
#define EPSV 1e-5f
#define COSEPS 1e-8f
#define TILE 64
#define DK   64           // k-chunk, double-buffered
#define SPAD 68           // padded smem row (floats), 272B = 16B-aligned
#define NTHR 512
#define NCHUNK (DIM / DK) // 8
#define NEGT 64u
#define NBLK 128u

#define SMEM_FLOATS (4 * DK * SPAD + 2 * DK)
#define SMEM_BYTES  (SMEM_FLOATS * 4)

// ---------------- device scratch (zero-initialized at load; last block re-zeros) --
__device__ float g_deno[NPOS];
__device__ float g_total;
__device__ unsigned g_negdone;
__device__ unsigned g_alldone;

__device__ __forceinline__ float warp_sum(float v) {
#pragma unroll
    for (int o = 16; o; o >>= 1) v += __shfl_xor_sync(0xffffffffu, v, o);
    return v;
}

__device__ __forceinline__ float sp(float x) {   // softplus, stable
    return fmaxf(x, 0.f) + log1pf(expf(-fabsf(x)));
}

// ---------------- single fused kernel ----------------
// grid (16, 8): bx<8 -> pos-vs-pos (loss1 + bce), bx>=8 -> pos-vs-neg (deno + bce)
// Prologue (register-scoped, runs BEFORE any mainloop prefetch) computes per-row
// stats (rnorm, t1+s3 | t2+s3). Mainloop = R12 verbatim.
// logit = (t1+s3)[n] + (t2+s3)[m] - 2*sum_d w_d*min(a,b) + bias
__global__ void __launch_bounds__(NTHR, 1) pair_kernel(
    const float* __restrict__ pos, const float* __restrict__ neg,
    const float* __restrict__ w, const float* __restrict__ bptr,
    float* __restrict__ out)
{
    extern __shared__ float smem[];
    float (*sA)[TILE][SPAD] = (float (*)[TILE][SPAD])(smem);             // [buf][row][d]
    float (*sB)[DK][SPAD]   = (float (*)[DK][SPAD])(smem + 2 * TILE * SPAD); // [buf][d][col]
    float (*sW)[DK]         = (float (*)[DK])(smem + 4 * DK * SPAD);
    __shared__ float sRNa[TILE], sT1[TILE], sRNb[TILE], sT2[TILE];
    __shared__ float sRed[16];
    __shared__ unsigned sLast;

    const int t  = threadIdx.x;
    const int tx = t & 15;           // m: 4 cols each
    const int ty = t >> 4;           // n: 2 rows each (0..31)
    const int n0 = blockIdx.y * TILE;
    const int m0 = blockIdx.x * TILE;
    const bool pos_half = (m0 < NPOS);
    const float* Bsrc = pos_half ? pos : neg;
    const int mrow0 = pos_half ? m0 : (m0 - NPOS);
    const float* w3 = w + 2 * DIM;

    // ---- prologue FIRST: row stats, all registers die before the mainloop ----
    {
        const int half = t >> 8;          // 0 = A rows (pos), 1 = B rows
        const int r    = (t & 255) >> 2;  // row 0..63
        const int tq   = t & 3;           // dim quarter
        const float* src = half ? (Bsrc + (mrow0 + r) * DIM) : (pos + (n0 + r) * DIM);
        const float* wx  = half ? (w + DIM) : w;      // w2 for B rows, w1 for A rows
        const float4* v4 = (const float4*)src + tq * 32;
        const float4* x4 = (const float4*)wx  + tq * 32;
        const float4* u4 = (const float4*)w3  + tq * 32;
        float ss = 0.f, dx = 0.f, d3 = 0.f;
#pragma unroll 4
        for (int q = 0; q < 32; q++) {
            float4 v = v4[q];
            float4 x = x4[q];
            float4 u = u4[q];
            ss = fmaf(v.x, v.x, ss); ss = fmaf(v.y, v.y, ss);
            ss = fmaf(v.z, v.z, ss); ss = fmaf(v.w, v.w, ss);
            dx = fmaf(v.x, x.x, dx); dx = fmaf(v.y, x.y, dx);
            dx = fmaf(v.z, x.z, dx); dx = fmaf(v.w, x.w, dx);
            d3 = fmaf(v.x, u.x, d3); d3 = fmaf(v.y, u.y, d3);
            d3 = fmaf(v.z, u.z, d3); d3 = fmaf(v.w, u.w, d3);
        }
        ss += __shfl_xor_sync(0xffffffffu, ss, 1);
        ss += __shfl_xor_sync(0xffffffffu, ss, 2);
        dx += __shfl_xor_sync(0xffffffffu, dx, 1);
        dx += __shfl_xor_sync(0xffffffffu, dx, 2);
        d3 += __shfl_xor_sync(0xffffffffu, d3, 1);
        d3 += __shfl_xor_sync(0xffffffffu, d3, 2);
        if (tq == 0) {
            float rn = 1.f / fmaxf(sqrtf(ss), COSEPS);
            if (half) { sRNb[r] = rn; sT2[r] = dx + d3; }
            else      { sRNa[r] = rn; sT1[r] = dx + d3; }
        }
    }

    float dotv[2][4], mnv[2][4];
#pragma unroll
    for (int i = 0; i < 2; i++)
#pragma unroll
        for (int j = 0; j < 4; j++) { dotv[i][j] = 0.f; mnv[i][j] = 0.f; }

    // A loader: row-contiguous float4s; B loader: R12 mapping
    const int arow = t >> 3;
    const int adq  = (t & 7) * 8;
    const int lc = t & 63;
    const int lr = t >> 6;

    float4 pfA0, pfA1;
    float pfB[8];
    float4 pfW;
#define LOADC(Dz) do {                                                    \
    pfA0 = *(const float4*)(pos + (n0 + arow) * DIM + (Dz) + adq);        \
    pfA1 = *(const float4*)(pos + (n0 + arow) * DIM + (Dz) + adq + 4);    \
    _Pragma("unroll")                                                     \
    for (int q = 0; q < 8; q++)                                           \
        pfB[q] = Bsrc[(mrow0 + lr + 8 * q) * DIM + (Dz) + lc];            \
    if (t < 16) pfW = *(const float4*)(w3 + (Dz) + t * 4);                \
} while (0)

#define STORC(buf) do {                                                   \
    *(float4*)&sA[buf][arow][adq]     = pfA0;                             \
    *(float4*)&sA[buf][arow][adq + 4] = pfA1;                             \
    _Pragma("unroll")                                                     \
    for (int q = 0; q < 8; q++)                                           \
        sB[buf][lc][lr + 8 * q] = pfB[q];                                 \
    if (t < 16) *(float4*)&sW[buf][t * 4] = pfW;                          \
} while (0)

    LOADC(0);
    STORC(0);
    __syncthreads();

    // ---- mainloop (identical to R12) ----
    for (int c = 0; c < NCHUNK; c++) {
        const int cur = c & 1;
        if (c < NCHUNK - 1) LOADC((c + 1) * DK);

#pragma unroll 4
        for (int kg = 0; kg < DK / 4; kg++) {
            const float4 wv4 = *(const float4*)&sW[cur][kg * 4];
            const float4 a0v = *(const float4*)&sA[cur][ty * 2]    [kg * 4];
            const float4 a1v = *(const float4*)&sA[cur][ty * 2 + 1][kg * 4];
            const float aw[2][4] = {{a0v.x, a0v.y, a0v.z, a0v.w},
                                    {a1v.x, a1v.y, a1v.z, a1v.w}};
            const float wk[4] = {wv4.x, wv4.y, wv4.z, wv4.w};
#pragma unroll
            for (int u = 0; u < 4; u++) {
                float4 bv = *(const float4*)&sB[cur][kg * 4 + u][tx * 4];
                float b[4] = {bv.x, bv.y, bv.z, bv.w};
#pragma unroll
                for (int i = 0; i < 2; i++)
#pragma unroll
                    for (int j = 0; j < 4; j++) {
                        dotv[i][j] = fmaf(aw[i][u], b[j], dotv[i][j]);
                        mnv[i][j]  = fmaf(fminf(aw[i][u], b[j]), wk[u], mnv[i][j]);
                    }
            }
        }

        if (c < NCHUNK - 1) STORC(1 - cur);
        __syncthreads();
    }

    // ---- epilogue ----
    int gn[2];
    float rn_n[2], t1v[2], rn_m[4], t2v[4];
#pragma unroll
    for (int i = 0; i < 2; i++) {
        gn[i] = n0 + ty * 2 + i;
        rn_n[i] = sRNa[ty * 2 + i];
        t1v[i]  = sT1[ty * 2 + i];
    }
#pragma unroll
    for (int j = 0; j < 4; j++) {
        rn_m[j] = sRNb[tx * 4 + j];
        t2v[j]  = sT2[tx * 4 + j];
    }
    float bias = __ldg(bptr);

    float part = 0.f;

    if (!pos_half) {
        // ---- negative half: bce(label 0) + deno ----
        float bce = 0.f, dl[2] = {0.f, 0.f};
#pragma unroll
        for (int i = 0; i < 2; i++) {
#pragma unroll
            for (int j = 0; j < 4; j++) {
                float cc = dotv[i][j] * rn_n[i] * rn_m[j];
                float logit = t1v[i] + t2v[j] - 2.f * mnv[i][j] + bias;
                bce += sp(logit);
                dl[i] += expf(cc);
            }
        }
#pragma unroll
        for (int i = 0; i < 2; i++) {
            float v = dl[i];
            v += __shfl_xor_sync(0xffffffffu, v, 1);
            v += __shfl_xor_sync(0xffffffffu, v, 2);
            v += __shfl_xor_sync(0xffffffffu, v, 4);
            v += __shfl_xor_sync(0xffffffffu, v, 8);
            if (tx == 0) atomicAdd(&g_deno[gn[i]], v);
        }
        __threadfence();                       // publish deno before negdone arrive
        part = bce * (1.0f / (float)NALL);
    } else {
        // ---- positive half: wait for deno, then bce(label 1) + contrastive ----
        if (t == 0) {
            while (atomicCAS(&g_negdone, NEGT, NEGT) != NEGT) { __nanosleep(200); }
        }
        __syncthreads();
        __threadfence();
        float dn[2];
#pragma unroll
        for (int i = 0; i < 2; i++) dn[i] = __ldcg(&g_deno[gn[i]]);

        float bce = 0.f, l1 = 0.f;
#pragma unroll
        for (int i = 0; i < 2; i++) {
#pragma unroll
            for (int j = 0; j < 4; j++) {
                float cc = dotv[i][j] * rn_n[i] * rn_m[j];
                float logit = t1v[i] + t2v[j] - 2.f * mnv[i][j] + bias;
                bce += sp(-logit);
                l1 += logf(dn[i] + expf(cc) + EPSV) - cc;  // -log(e^c/(deno+e^c+eps))
            }
        }
        part = bce * (1.0f / (float)NALL) + l1;
    }

    // ---- block reduce + global accumulate + completion + replay reset ----
    float v = warp_sum(part);
    if ((t & 31) == 0) sRed[t >> 5] = v;
    __syncthreads();
    if (t == 0) {
        float s = 0.f;
#pragma unroll
        for (int k = 0; k < 16; k++) s += sRed[k];
        atomicAdd(&g_total, s);
        __threadfence();
        if (!pos_half) atomicAdd(&g_negdone, 1u);
        unsigned old = atomicAdd(&g_alldone, 1u);
        sLast = (old == NBLK - 1u) ? 1u : 0u;
    }
    __syncthreads();
    if (sLast) {
        // last block: emit result and reset all globals for the next graph replay
        g_deno[t] = 0.f;                       // 512 threads cover NPOS exactly
        if (t == 0) {
            __threadfence();
            out[0] = atomicAdd(&g_total, 0.f);
            g_total = 0.f;
            g_negdone = 0u;
            g_alldone = 0u;
        }
    }
}

// ---------------- launch ----------------
extern "C" void kernel_launch(void* const* d_in, const int* in_sizes, int n_in,
                              void* d_out, int out_size) {
    const float* pos = (const float*)d_in[0];   // [512,512]
    const float* neg = (const float*)d_in[1];   // [512,512]
    const float* w   = (const float*)d_in[2];   // [1,1536]
    const float* b   = (const float*)d_in[3];   // [1]
    float* out = (float*)d_out;

    cudaFuncSetAttribute(pair_kernel,
                         cudaFuncAttributeMaxDynamicSharedMemorySize, SMEM_BYTES);

    dim3 grid(NALL / TILE, NPOS / TILE);        // (16, 8) — one wave, 128 blocks
    pair_kernel<<<grid, NTHR, SMEM_BYTES>>>(pos, neg, w, b, out);
}

// round 16
// speedup vs baseline: 1.2750x; 1.2750x over previous
#include <cuda_runtime.h>
#include <math.h>

#define NPOS 512
#define NALL 1024
#define DIM  512
#define EPSV 1e-5f
#define COSEPS 1e-8f
#define TILE 64
#define DK   64           // k-chunk, double-buffered
#define SPAD 68           // padded smem row (floats), 272B = 16B-aligned
#define NTHR 512
#define NCHUNK (DIM / DK) // 8
#define NEGT 64u
#define NBLK 128u

#define SMEM_FLOATS (4 * DK * SPAD + 2 * DK)
#define SMEM_BYTES  (SMEM_FLOATS * 4)

// ---------------- device scratch (zero-init at load; last block re-zeros counters)
__device__ float g_rnorm[NALL];
__device__ float g_t1[NPOS];     // t1 + s3 (pos rows)
__device__ float g_t2[NALL];     // t2 + s3 (all rows)
__device__ float g_deno[NPOS];
__device__ float g_total;
__device__ unsigned g_statdone;
__device__ unsigned g_negdone;
__device__ unsigned g_alldone;

__device__ __forceinline__ float warp_sum(float v) {
#pragma unroll
    for (int o = 16; o; o >>= 1) v += __shfl_xor_sync(0xffffffffu, v, o);
    return v;
}

__device__ __forceinline__ float sp(float x) {   // softplus, stable
    return fmaxf(x, 0.f) + log1pf(expf(-fabsf(x)));
}

// ---------------- single fused kernel ----------------
// grid (16, 8): bx<8 -> pos-vs-pos (loss1 + bce), bx>=8 -> pos-vs-neg (deno + bce)
// Prologue: each block computes stats for 8 DISTINCT rows (no chip-wide redundancy),
// publishes via g_statdone. Mainloop = R12 verbatim. Stats consumed post-mainloop.
// logit = (t1+s3)[n] + (t2+s3)[m] - 2*sum_d w_d*min(a,b) + bias
__global__ void __launch_bounds__(NTHR, 1) pair_kernel(
    const float* __restrict__ pos, const float* __restrict__ neg,
    const float* __restrict__ w, const float* __restrict__ bptr,
    float* __restrict__ out)
{
    extern __shared__ float smem[];
    float (*sA)[TILE][SPAD] = (float (*)[TILE][SPAD])(smem);             // [buf][row][d]
    float (*sB)[DK][SPAD]   = (float (*)[DK][SPAD])(smem + 2 * TILE * SPAD); // [buf][d][col]
    float (*sW)[DK]         = (float (*)[DK])(smem + 4 * DK * SPAD);
    __shared__ float sPr[8][2][4];
    __shared__ float sRed[16];
    __shared__ unsigned sLast;

    const int t  = threadIdx.x;
    const int tx = t & 15;           // m: 4 cols each
    const int ty = t >> 4;           // n: 2 rows each (0..31)
    const int n0 = blockIdx.y * TILE;
    const int m0 = blockIdx.x * TILE;
    const bool pos_half = (m0 < NPOS);
    const float* Bsrc = pos_half ? pos : neg;
    const int mrow0 = pos_half ? m0 : (m0 - NPOS);
    const float* w3 = w + 2 * DIM;
    const int bid = blockIdx.y * gridDim.x + blockIdx.x;   // 0..127

    // ---- prologue: stats for rows [8*bid, 8*bid+8) — each row computed ONCE chip-wide
    {
        const int prow = t >> 6;         // 0..7
        const int pl   = t & 63;         // 64 threads per row; dims pl*8..pl*8+7
        const int grow = bid * 8 + prow; // 0..1023
        const float* src = (grow < NPOS) ? (pos + grow * DIM) : (neg + (grow - NPOS) * DIM);
        const float4* v4  = (const float4*)src       + pl * 2;
        const float4* w1v = (const float4*)w         + pl * 2;
        const float4* w2v = (const float4*)(w + DIM) + pl * 2;
        const float4* w3v = (const float4*)w3        + pl * 2;
        float ss = 0.f, d1 = 0.f, d2 = 0.f, d3 = 0.f;
#pragma unroll
        for (int q = 0; q < 2; q++) {
            float4 v = v4[q], a = w1v[q], b = w2v[q], c = w3v[q];
            ss = fmaf(v.x, v.x, ss); ss = fmaf(v.y, v.y, ss);
            ss = fmaf(v.z, v.z, ss); ss = fmaf(v.w, v.w, ss);
            d1 = fmaf(v.x, a.x, d1); d1 = fmaf(v.y, a.y, d1);
            d1 = fmaf(v.z, a.z, d1); d1 = fmaf(v.w, a.w, d1);
            d2 = fmaf(v.x, b.x, d2); d2 = fmaf(v.y, b.y, d2);
            d2 = fmaf(v.z, b.z, d2); d2 = fmaf(v.w, b.w, d2);
            d3 = fmaf(v.x, c.x, d3); d3 = fmaf(v.y, c.y, d3);
            d3 = fmaf(v.z, c.z, d3); d3 = fmaf(v.w, c.w, d3);
        }
        ss = warp_sum(ss); d1 = warp_sum(d1); d2 = warp_sum(d2); d3 = warp_sum(d3);
        const int wh = (t >> 5) & 1;     // which warp-half of this row
        if ((t & 31) == 0) {
            sPr[prow][wh][0] = ss; sPr[prow][wh][1] = d1;
            sPr[prow][wh][2] = d2; sPr[prow][wh][3] = d3;
        }
        __syncthreads();
        if (t < 8) {
            const int gr = bid * 8 + t;
            float S  = sPr[t][0][0] + sPr[t][1][0];
            float D1 = sPr[t][0][1] + sPr[t][1][1];
            float D2 = sPr[t][0][2] + sPr[t][1][2];
            float D3 = sPr[t][0][3] + sPr[t][1][3];
            g_rnorm[gr] = 1.f / fmaxf(sqrtf(S), COSEPS);
            g_t2[gr] = D2 + D3;
            if (gr < NPOS) g_t1[gr] = D1 + D3;
        }
        __syncthreads();
        if (t == 0) { __threadfence(); atomicAdd(&g_statdone, 1u); }
    }

    float dotv[2][4], mnv[2][4];
#pragma unroll
    for (int i = 0; i < 2; i++)
#pragma unroll
        for (int j = 0; j < 4; j++) { dotv[i][j] = 0.f; mnv[i][j] = 0.f; }

    // A loader: row-contiguous float4s; B loader: R12 mapping
    const int arow = t >> 3;
    const int adq  = (t & 7) * 8;
    const int lc = t & 63;
    const int lr = t >> 6;

    float4 pfA0, pfA1;
    float pfB[8];
    float4 pfW;
#define LOADC(Dz) do {                                                    \
    pfA0 = *(const float4*)(pos + (n0 + arow) * DIM + (Dz) + adq);        \
    pfA1 = *(const float4*)(pos + (n0 + arow) * DIM + (Dz) + adq + 4);    \
    _Pragma("unroll")                                                     \
    for (int q = 0; q < 8; q++)                                           \
        pfB[q] = Bsrc[(mrow0 + lr + 8 * q) * DIM + (Dz) + lc];            \
    if (t < 16) pfW = *(const float4*)(w3 + (Dz) + t * 4);                \
} while (0)

#define STORC(buf) do {                                                   \
    *(float4*)&sA[buf][arow][adq]     = pfA0;                             \
    *(float4*)&sA[buf][arow][adq + 4] = pfA1;                             \
    _Pragma("unroll")                                                     \
    for (int q = 0; q < 8; q++)                                           \
        sB[buf][lc][lr + 8 * q] = pfB[q];                                 \
    if (t < 16) *(float4*)&sW[buf][t * 4] = pfW;                          \
} while (0)

    LOADC(0);
    STORC(0);
    __syncthreads();

    // ---- mainloop (identical to R12) ----
    for (int c = 0; c < NCHUNK; c++) {
        const int cur = c & 1;
        if (c < NCHUNK - 1) LOADC((c + 1) * DK);

#pragma unroll 4
        for (int kg = 0; kg < DK / 4; kg++) {
            const float4 wv4 = *(const float4*)&sW[cur][kg * 4];
            const float4 a0v = *(const float4*)&sA[cur][ty * 2]    [kg * 4];
            const float4 a1v = *(const float4*)&sA[cur][ty * 2 + 1][kg * 4];
            const float aw[2][4] = {{a0v.x, a0v.y, a0v.z, a0v.w},
                                    {a1v.x, a1v.y, a1v.z, a1v.w}};
            const float wk[4] = {wv4.x, wv4.y, wv4.z, wv4.w};
#pragma unroll
            for (int u = 0; u < 4; u++) {
                float4 bv = *(const float4*)&sB[cur][kg * 4 + u][tx * 4];
                float b[4] = {bv.x, bv.y, bv.z, bv.w};
#pragma unroll
                for (int i = 0; i < 2; i++)
#pragma unroll
                    for (int j = 0; j < 4; j++) {
                        dotv[i][j] = fmaf(aw[i][u], b[j], dotv[i][j]);
                        mnv[i][j]  = fmaf(fminf(aw[i][u], b[j]), wk[u], mnv[i][j]);
                    }
            }
        }

        if (c < NCHUNK - 1) STORC(1 - cur);
        __syncthreads();
    }

    // ---- wait for all row stats (published ~1us in; mainloop took ~40us: no wait)
    if (t == 0) {
        while (atomicCAS(&g_statdone, NBLK, NBLK) != NBLK) { __nanosleep(100); }
    }
    __syncthreads();
    __threadfence();

    // ---- epilogue ----
    int gn[2];
    float rn_n[2], t1v[2], rn_m[4], t2v[4];
#pragma unroll
    for (int i = 0; i < 2; i++) {
        gn[i] = n0 + ty * 2 + i;
        rn_n[i] = __ldcg(&g_rnorm[gn[i]]);
        t1v[i]  = __ldcg(&g_t1[gn[i]]);    // includes s3[n]
    }
#pragma unroll
    for (int j = 0; j < 4; j++) {
        int gm = m0 + tx * 4 + j;
        rn_m[j] = __ldcg(&g_rnorm[gm]);
        t2v[j]  = __ldcg(&g_t2[gm]);       // includes s3[m]
    }
    float bias = __ldg(bptr);

    float part = 0.f;

    if (!pos_half) {
        // ---- negative half: bce(label 0) + deno ----
        float bce = 0.f, dl[2] = {0.f, 0.f};
#pragma unroll
        for (int i = 0; i < 2; i++) {
#pragma unroll
            for (int j = 0; j < 4; j++) {
                float cc = dotv[i][j] * rn_n[i] * rn_m[j];
                float logit = t1v[i] + t2v[j] - 2.f * mnv[i][j] + bias;
                bce += sp(logit);
                dl[i] += expf(cc);
            }
        }
#pragma unroll
        for (int i = 0; i < 2; i++) {
            float v = dl[i];
            v += __shfl_xor_sync(0xffffffffu, v, 1);
            v += __shfl_xor_sync(0xffffffffu, v, 2);
            v += __shfl_xor_sync(0xffffffffu, v, 4);
            v += __shfl_xor_sync(0xffffffffu, v, 8);
            if (tx == 0) atomicAdd(&g_deno[gn[i]], v);
        }
        __threadfence();                       // publish deno before negdone arrive
        part = bce * (1.0f / (float)NALL);
    } else {
        // ---- positive half: wait for deno, then bce(label 1) + contrastive ----
        if (t == 0) {
            while (atomicCAS(&g_negdone, NEGT, NEGT) != NEGT) { __nanosleep(200); }
        }
        __syncthreads();
        __threadfence();
        float dn[2];
#pragma unroll
        for (int i = 0; i < 2; i++) dn[i] = __ldcg(&g_deno[gn[i]]);

        float bce = 0.f, l1 = 0.f;
#pragma unroll
        for (int i = 0; i < 2; i++) {
#pragma unroll
            for (int j = 0; j < 4; j++) {
                float cc = dotv[i][j] * rn_n[i] * rn_m[j];
                float logit = t1v[i] + t2v[j] - 2.f * mnv[i][j] + bias;
                bce += sp(-logit);
                l1 += logf(dn[i] + expf(cc) + EPSV) - cc;  // -log(e^c/(deno+e^c+eps))
            }
        }
        part = bce * (1.0f / (float)NALL) + l1;
    }

    // ---- block reduce + global accumulate + completion + replay reset ----
    float v = warp_sum(part);
    if ((t & 31) == 0) sRed[t >> 5] = v;
    __syncthreads();
    if (t == 0) {
        float s = 0.f;
#pragma unroll
        for (int k = 0; k < 16; k++) s += sRed[k];
        atomicAdd(&g_total, s);
        __threadfence();
        if (!pos_half) atomicAdd(&g_negdone, 1u);
        unsigned old = atomicAdd(&g_alldone, 1u);
        sLast = (old == NBLK - 1u) ? 1u : 0u;
    }
    __syncthreads();
    if (sLast) {
        // last block: emit result and reset globals for the next graph replay
        g_deno[t] = 0.f;                       // 512 threads cover NPOS exactly
        if (t == 0) {
            __threadfence();
            out[0] = atomicAdd(&g_total, 0.f);
            g_total = 0.f;
            g_statdone = 0u;
            g_negdone = 0u;
            g_alldone = 0u;
        }
    }
}

// ---------------- launch ----------------
extern "C" void kernel_launch(void* const* d_in, const int* in_sizes, int n_in,
                              void* d_out, int out_size) {
    const float* pos = (const float*)d_in[0];   // [512,512]
    const float* neg = (const float*)d_in[1];   // [512,512]
    const float* w   = (const float*)d_in[2];   // [1,1536]
    const float* b   = (const float*)d_in[3];   // [1]
    float* out = (float*)d_out;

    cudaFuncSetAttribute(pair_kernel,
                         cudaFuncAttributeMaxDynamicSharedMemorySize, SMEM_BYTES);

    dim3 grid(NALL / TILE, NPOS / TILE);        // (16, 8) — one wave, 128 blocks
    pair_kernel<<<grid, NTHR, SMEM_BYTES>>>(pos, neg, w, b, out);
}